// round 5
// baseline (speedup 1.0000x reference)
#include <cuda_runtime.h>
#include <cuda_fp16.h>
#include <cstdint>
#include <cstddef>

// ============================================================================
// EnhancedGNNEncoder: 2x GCNConv(+BN+ReLU) + GCNConv mu / GCNConv logstd
//   N=100000, E=3200000, dims 81 -> 64 -> 64 -> {32|32}
// R4 changes vs R3 (420us):
//   - Feature table g_A stored fp16 (gather traffic per agg pass halves).
//   - Agg: quarter-warp gather, 4 neighbors/iter, 1 shfl.idx per 4 neighbors,
//     LDG.128 per lane, fp32 accumulation, butterfly (xor8, xor16) combine.
//   - b1/b2 removed: bias cancels exactly through BatchNorm.
// ============================================================================

#define MAXN 100000
#define MAXE 3200000

__device__ int   g_deg[MAXN];
__device__ int   g_rowptr[MAXN];
__device__ int   g_next[MAXN];
__device__ int   g_srcs[MAXE];
__device__ float g_dis[MAXN];
__device__ uint4 g_A4[(size_t)MAXN * 8];   // fp16 feature table, 8x uint4 = 64 halves/row
__device__ float g_B[(size_t)MAXN * 64];   // aggregation outputs (BN inputs), fp32
__device__ float g_stats[2 * 128];         // per BN layer: sum(64) | sumsq(64)
__device__ int   g_blocksum[1024];
__device__ int   g_is64;

#define G_AH ((__half*)g_A4)

// ---------------------------------------------------------------------------
// dtype probe: int64 edge_index has zero high words.
// ---------------------------------------------------------------------------
__global__ void k_detect(const unsigned* __restrict__ p) {
    unsigned acc = 0;
    for (int k = threadIdx.x; k < 2048; k += 256) acc |= p[2 * k + 1];
#pragma unroll
    for (int off = 16; off; off >>= 1) acc |= __shfl_xor_sync(0xffffffffu, acc, off);
    __shared__ unsigned w[8];
    if ((threadIdx.x & 31) == 0) w[threadIdx.x >> 5] = acc;
    __syncthreads();
    if (threadIdx.x == 0) {
        unsigned t = 0;
#pragma unroll
        for (int i = 0; i < 8; i++) t |= w[i];
        g_is64 = (t == 0) ? 1 : 0;
    }
}

__global__ void k_init(int n) {
    int i = blockIdx.x * blockDim.x + threadIdx.x;
    if (i < n)   g_deg[i] = 0;
    if (i < 256) g_stats[i] = 0.f;
}

__device__ __forceinline__ int edge_dst(const void* ei, int e, int E, int is64) {
    if (is64) return (int)((const long long*)ei)[(long long)E + e];
    return ((const int*)ei)[E + e];
}
__device__ __forceinline__ int edge_src(const void* ei, int e, int E, int is64) {
    if (is64) return (int)((const long long*)ei)[e];
    return ((const int*)ei)[e];
}

__global__ void k_deg(const void* __restrict__ ei, int E) {
    int e = blockIdx.x * blockDim.x + threadIdx.x;
    if (e >= E) return;
    atomicAdd(&g_deg[edge_dst(ei, e, E, g_is64)], 1);
}

__global__ void k_scan1(int n) {
    const int t = threadIdx.x;
    const int base = blockIdx.x * 1024;
    int i0 = base + t * 4;
    int v0 = (i0 + 0 < n) ? g_deg[i0 + 0] : 0;
    int v1 = (i0 + 1 < n) ? g_deg[i0 + 1] : 0;
    int v2 = (i0 + 2 < n) ? g_deg[i0 + 2] : 0;
    int v3 = (i0 + 3 < n) ? g_deg[i0 + 3] : 0;
    int tsum = v0 + v1 + v2 + v3;
    int lane = t & 31, w = t >> 5;
    int incl = tsum;
#pragma unroll
    for (int off = 1; off < 32; off <<= 1) {
        int x = __shfl_up_sync(0xffffffffu, incl, off);
        if (lane >= off) incl += x;
    }
    __shared__ int wsum[8];
    if (lane == 31) wsum[w] = incl;
    __syncthreads();
    if (t < 8) {
        int x = wsum[t];
        int s = x;
#pragma unroll
        for (int off = 1; off < 8; off <<= 1) {
            int y = __shfl_up_sync(0xffu, s, off);
            if (t >= off) s += y;
        }
        wsum[t] = s - x;
    }
    __syncthreads();
    int texcl = wsum[w] + incl - tsum;
    if (i0 + 0 < n) g_rowptr[i0 + 0] = texcl;
    if (i0 + 1 < n) g_rowptr[i0 + 1] = texcl + v0;
    if (i0 + 2 < n) g_rowptr[i0 + 2] = texcl + v0 + v1;
    if (i0 + 3 < n) g_rowptr[i0 + 3] = texcl + v0 + v1 + v2;
    if (t == 255) g_blocksum[blockIdx.x] = texcl + tsum;
}

__global__ void k_scan2(int nb) {
    int t = threadIdx.x;
    __shared__ int sh[128];
    int v = (t < nb) ? g_blocksum[t] : 0;
    sh[t] = v;
    __syncthreads();
    for (int off = 1; off < 128; off <<= 1) {
        int x = (t >= off) ? sh[t - off] : 0;
        __syncthreads();
        sh[t] += x;
        __syncthreads();
    }
    if (t < nb) g_blocksum[t] = sh[t] - v;
}

__global__ void k_scan3(int n) {
    int i = blockIdx.x * blockDim.x + threadIdx.x;
    if (i >= n) return;
    int rp = g_rowptr[i] + g_blocksum[i >> 10];
    g_rowptr[i] = rp;
    g_next[i] = rp;
    g_dis[i] = rsqrtf((float)(g_deg[i] + 1));
}

__global__ void k_fill(const void* __restrict__ ei, int E) {
    int e = blockIdx.x * blockDim.x + threadIdx.x;
    if (e >= E) return;
    const int is64 = g_is64;
    int s = edge_src(ei, e, E, is64);
    int d = edge_dst(ei, e, E, is64);
    int pos = atomicAdd(&g_next[d], 1);
    g_srcs[pos] = s;
}

__device__ __forceinline__ void store_half4(size_t elem_off, float4 o) {
    __half2 h0 = __floats2half2_rn(o.x, o.y);
    __half2 h1 = __floats2half2_rn(o.z, o.w);
    uint2 u;
    u.x = *(const unsigned*)&h0;
    u.y = *(const unsigned*)&h1;
    *(uint2*)&G_AH[elem_off] = u;
}

// ---------------------------------------------------------------------------
// GEMM1: g_A[r] = fp16( dis[r] * (x[r,81] @ W1[81,64]) ). 4x4 register tiling.
// ---------------------------------------------------------------------------
__global__ void k_gemm81(const float* __restrict__ x, const float* __restrict__ W, int n) {
    __shared__ float Ws[81 * 64];
    __shared__ float Xs[81 * 68];   // [k][row]
    __shared__ float ds[64];
    const int t = threadIdx.x;          // 256
    const int r0b = blockIdx.x * 64;
    for (int i = t; i < 81 * 64; i += 256) Ws[i] = W[i];
    if (t < 64) { int r = r0b + t; ds[t] = (r < n) ? g_dis[r] : 0.f; }
    {
        size_t gbase = (size_t)r0b * 81;
        size_t lim = (size_t)n * 81;
        for (int i = t; i < 64 * 81; i += 256) {
            size_t g = gbase + i;
            float v = (g < lim) ? x[g] : 0.f;
            int row = i / 81, k = i - row * 81;
            Xs[k * 68 + row] = v;
        }
    }
    __syncthreads();
    const int lr = (t >> 4) * 4;
    const int c0 = (t & 15) * 4;
    float4 a0 = {0,0,0,0}, a1 = {0,0,0,0}, a2 = {0,0,0,0}, a3 = {0,0,0,0};
#pragma unroll 3
    for (int k = 0; k < 81; k++) {
        float4 xv = *(const float4*)&Xs[k * 68 + lr];
        float4 wv = *(const float4*)&Ws[k * 64 + c0];
        a0.x += xv.x * wv.x; a0.y += xv.x * wv.y; a0.z += xv.x * wv.z; a0.w += xv.x * wv.w;
        a1.x += xv.y * wv.x; a1.y += xv.y * wv.y; a1.z += xv.y * wv.z; a1.w += xv.y * wv.w;
        a2.x += xv.z * wv.x; a2.y += xv.z * wv.y; a2.z += xv.z * wv.z; a2.w += xv.z * wv.w;
        a3.x += xv.w * wv.x; a3.y += xv.w * wv.y; a3.z += xv.w * wv.z; a3.w += xv.w * wv.w;
    }
    float4 accs[4] = {a0, a1, a2, a3};
#pragma unroll
    for (int j = 0; j < 4; j++) {
        int r = r0b + lr + j;
        if (r < n) {
            float d = ds[lr + j];
            float4 o = accs[j];
            o.x *= d; o.y *= d; o.z *= d; o.w *= d;
            store_half4((size_t)r * 64 + c0, o);
        }
    }
}

// ---------------------------------------------------------------------------
// GEMM64: g_A[r] = fp16( dis[r] * (BNReLU(g_B)[r,64] @ W[64,64]) )
//   BN scale/shift computed inline from g_stats[bnIdx]. W = Wa or [Wa|Wb].
// ---------------------------------------------------------------------------
__global__ void k_gemm64(const float* __restrict__ Wa, const float* __restrict__ Wb,
                         const float* __restrict__ gamma, const float* __restrict__ beta,
                         int bnIdx, int n, float invn) {
    __shared__ float Ws[64 * 64];
    __shared__ float Xs[64 * 68];
    __shared__ float ssc[64], ssh[64], ds[64];
    const int t = threadIdx.x;          // 256
    const int r0b = blockIdx.x * 64;
    if (t < 64) {
        float sum = g_stats[bnIdx * 128 + t];
        float sq  = g_stats[bnIdx * 128 + 64 + t];
        float m   = sum * invn;
        float var = sq * invn - m * m;
        float sc  = gamma[t] * rsqrtf(var + 1e-5f);
        ssc[t] = sc;
        ssh[t] = beta[t] - m * sc;
        int r = r0b + t; ds[t] = (r < n) ? g_dis[r] : 0.f;
    }
    for (int i = t; i < 4096; i += 256) {
        int k = i >> 6, c = i & 63;
        Ws[i] = Wb ? ((c < 32) ? Wa[k * 32 + c] : Wb[k * 32 + (c - 32)]) : Wa[i];
    }
    __syncthreads();
    for (int i = t; i < 4096; i += 256) {
        int row = i >> 6, k = i & 63;
        int r = r0b + row;
        float v = 0.f;
        if (r < n) {
            v = g_B[(size_t)r * 64 + k];
            v = fmaxf(fmaf(v, ssc[k], ssh[k]), 0.f);
        }
        Xs[k * 68 + row] = v;
    }
    __syncthreads();
    const int lr = (t >> 4) * 4;
    const int c0 = (t & 15) * 4;
    float4 a0 = {0,0,0,0}, a1 = {0,0,0,0}, a2 = {0,0,0,0}, a3 = {0,0,0,0};
#pragma unroll 4
    for (int k = 0; k < 64; k++) {
        float4 xv = *(const float4*)&Xs[k * 68 + lr];
        float4 wv = *(const float4*)&Ws[k * 64 + c0];
        a0.x += xv.x * wv.x; a0.y += xv.x * wv.y; a0.z += xv.x * wv.z; a0.w += xv.x * wv.w;
        a1.x += xv.y * wv.x; a1.y += xv.y * wv.y; a1.z += xv.y * wv.z; a1.w += xv.y * wv.w;
        a2.x += xv.z * wv.x; a2.y += xv.z * wv.y; a2.z += xv.z * wv.z; a2.w += xv.z * wv.w;
        a3.x += xv.w * wv.x; a3.y += xv.w * wv.y; a3.z += xv.w * wv.z; a3.w += xv.w * wv.w;
    }
    float4 accs[4] = {a0, a1, a2, a3};
#pragma unroll
    for (int j = 0; j < 4; j++) {
        int r = r0b + lr + j;
        if (r < n) {
            float d = ds[lr + j];
            float4 o = accs[j];
            o.x *= d; o.y *= d; o.z *= d; o.w *= d;
            store_half4((size_t)r * 64 + c0, o);
        }
    }
}

// ---------------------------------------------------------------------------
// Aggregation: one warp per node, quarter-warp fp16 gather, 4 neighbors/iter.
//   out[i] = dis[i] * (Ascaled[i] + sum_{s in N(i)} Ascaled[s]) [+ bias mode 2]
//   mode 0/1 -> g_B + BN stats (no bias: cancels through BN)
//   mode 2   -> split mu | logstd to dout with biases.
// ---------------------------------------------------------------------------
__global__ void k_agg(float* __restrict__ dout, const float* __restrict__ bias,
                      const float* __restrict__ bias2, int n, int mode) {
    const int w    = (blockIdx.x * blockDim.x + threadIdx.x) >> 5;
    const int lane = threadIdx.x & 31;
    const int hb   = lane >> 3;          // quarter index: neighbor slot parity
    const int cg   = lane & 7;           // 16B column group (8 halves)
    __shared__ float ssum[64], ssq[64];
    if (mode < 2) {
        if (threadIdx.x < 64) { ssum[threadIdx.x] = 0.f; ssq[threadIdx.x] = 0.f; }
        __syncthreads();
    }
    float acc[8] = {0,0,0,0,0,0,0,0};
    const bool active = (w < n);
    if (active) {
        const int beg = g_rowptr[w];
        const int cnt = g_deg[w];
        int j = 0;
        while (j < cnt) {
            int m = cnt - j; if (m > 32) m = 32;
            int myS = (lane < m) ? g_srcs[beg + j + lane] : 0;
#pragma unroll 2
            for (int p = 0; p < 8; p++) {
                if (4 * p >= m) break;
                int idx = 4 * p + hb;
                int s = __shfl_sync(0xffffffffu, myS, idx);
                if (idx < m) {
                    uint4 u = g_A4[(size_t)s * 8 + cg];
                    float2 f0 = __half22float2(*(const __half2*)&u.x);
                    float2 f1 = __half22float2(*(const __half2*)&u.y);
                    float2 f2 = __half22float2(*(const __half2*)&u.z);
                    float2 f3 = __half22float2(*(const __half2*)&u.w);
                    acc[0] += f0.x; acc[1] += f0.y;
                    acc[2] += f1.x; acc[3] += f1.y;
                    acc[4] += f2.x; acc[5] += f2.y;
                    acc[6] += f3.x; acc[7] += f3.y;
                }
            }
            j += m;
        }
    }
    // combine the 4 quarter-warp partials (lanes l, l+8, l+16, l+24 share cols)
#pragma unroll
    for (int i = 0; i < 8; i++) {
        acc[i] += __shfl_xor_sync(0xffffffffu, acc[i], 8);
        acc[i] += __shfl_xor_sync(0xffffffffu, acc[i], 16);
    }

    if (active && hb == 0) {             // lanes 0..7 hold final 8 cols each
        const float di = g_dis[w];
        uint4 su = g_A4[(size_t)w * 8 + cg];
        float2 s0 = __half22float2(*(const __half2*)&su.x);
        float2 s1 = __half22float2(*(const __half2*)&su.y);
        float2 s2 = __half22float2(*(const __half2*)&su.z);
        float2 s3 = __half22float2(*(const __half2*)&su.w);
        float o[8];
        o[0] = di * (acc[0] + s0.x); o[1] = di * (acc[1] + s0.y);
        o[2] = di * (acc[2] + s1.x); o[3] = di * (acc[3] + s1.y);
        o[4] = di * (acc[4] + s2.x); o[5] = di * (acc[5] + s2.y);
        o[6] = di * (acc[6] + s3.x); o[7] = di * (acc[7] + s3.y);
        if (mode < 2) {
            float4* dst = (float4*)&g_B[(size_t)w * 64 + cg * 8];
            dst[0] = make_float4(o[0], o[1], o[2], o[3]);
            dst[1] = make_float4(o[4], o[5], o[6], o[7]);
            int c = cg * 8;
#pragma unroll
            for (int i = 0; i < 8; i++) {
                atomicAdd(&ssum[c + i], o[i]);
                atomicAdd(&ssq[c + i], o[i] * o[i]);
            }
        } else {
            if (cg < 4) {                // columns 0..31 -> mu
                const float* b = bias + cg * 8;
                float4* dst = (float4*)&dout[(size_t)w * 32 + cg * 8];
                dst[0] = make_float4(o[0] + b[0], o[1] + b[1], o[2] + b[2], o[3] + b[3]);
                dst[1] = make_float4(o[4] + b[4], o[5] + b[5], o[6] + b[6], o[7] + b[7]);
            } else {                     // columns 32..63 -> logstd
                const float* b = bias2 + (cg - 4) * 8;
                float4* dst = (float4*)&dout[(size_t)n * 32 + (size_t)w * 32 + (cg - 4) * 8];
                dst[0] = make_float4(o[0] + b[0], o[1] + b[1], o[2] + b[2], o[3] + b[3]);
                dst[1] = make_float4(o[4] + b[4], o[5] + b[5], o[6] + b[6], o[7] + b[7]);
            }
        }
    }
    if (mode < 2) {
        __syncthreads();
        if (threadIdx.x < 64) {
            atomicAdd(&g_stats[mode * 128 + threadIdx.x],      ssum[threadIdx.x]);
            atomicAdd(&g_stats[mode * 128 + 64 + threadIdx.x], ssq[threadIdx.x]);
        }
    }
}

// ---------------------------------------------------------------------------
extern "C" void kernel_launch(void* const* d_in, const int* in_sizes, int n_in,
                              void* d_out, int out_size) {
    const float* x     = (const float*)d_in[0];
    const void*  ei    = d_in[1];
    const float* W1    = (const float*)d_in[2];
    const float* g1    = (const float*)d_in[4];
    const float* beta1 = (const float*)d_in[5];
    const float* W2    = (const float*)d_in[6];
    const float* g2    = (const float*)d_in[8];
    const float* beta2 = (const float*)d_in[9];
    const float* Wmu   = (const float*)d_in[10];
    const float* bmu   = (const float*)d_in[11];
    const float* Wls   = (const float*)d_in[12];
    const float* bls   = (const float*)d_in[13];
    float* out = (float*)d_out;

    const int n = in_sizes[0] / 81;
    const int E = in_sizes[1] / 2;
    const float invn = 1.0f / (float)n;

    const int TB = 256;
    const int nBlkN  = (n + TB - 1) / TB;
    const int nBlkE  = (E + TB - 1) / TB;
    const int nbScan = (n + 1023) / 1024;
    const int nBlkG  = (n + 63) / 64;
    const int nBlkW  = (n + 7) / 8;      // agg: 1 warp/node, 8 warps/block

    // Graph build
    k_detect<<<1, 256>>>((const unsigned*)ei);
    k_init<<<nBlkN, TB>>>(n);
    k_deg<<<nBlkE, TB>>>(ei, E);
    k_scan1<<<nbScan, 256>>>(n);
    k_scan2<<<1, 128>>>(nbScan);
    k_scan3<<<nBlkN, TB>>>(n);
    k_fill<<<nBlkE, TB>>>(ei, E);

    // Layer 1
    k_gemm81<<<nBlkG, 256>>>(x, W1, n);
    k_agg<<<nBlkW, TB>>>(nullptr, nullptr, nullptr, n, 0);

    // Layer 2
    k_gemm64<<<nBlkG, 256>>>(W2, nullptr, g1, beta1, 0, n, invn);
    k_agg<<<nBlkW, TB>>>(nullptr, nullptr, nullptr, n, 1);

    // mu / logstd (fused concat weights)
    k_gemm64<<<nBlkG, 256>>>(Wmu, Wls, g2, beta2, 1, n, invn);
    k_agg<<<nBlkW, TB>>>(out, bmu, bls, n, 2);
}